// round 3
// baseline (speedup 1.0000x reference)
#include <cuda_runtime.h>
#include <math_constants.h>

// VQ-VAE vector quantizer. Bitwise-emulates the reference fp32 pipeline:
//   d_k = fl32( fl32(A - 2*M_k) + B_k )
//   A   = sum(x^2)  (XLA GPU row-reduce order: float2 leaves + shfl tree)
//   M_k = x . e_k   (sequential ascending-d fp32 FMA chain from 0)
//   B_k = sum(e^2)  (sequential ascending chain)
//   argmin with tie -> lowest index. ALL arithmetic orders frozen (rel_err==0).
//
// This round: MOV-free packed-f32x2 mainloop via duplicated transposed
// codebook in global scratch + 16B shared loads; packed fold; merged final.

#define K_CODES   1024
#define D_DIM     64
#define TP        128     // positions per block
#define TK        128     // codes per chunk
#define EROW      130     // EsDup row stride in pairs (16B-aligned, conflict-limited)
#define ENC_OFF   4194304
#define LOSS_OFF  4259840
#define NLL_OFF   4259841
#define TOTAL_OUT 4259842

typedef unsigned long long ull;

__device__ double g_loss_acc;
__device__ int    g_done;
__device__ float  g_eB[K_CODES];                       // fp32 ||e_k||^2, sequential chain
__device__ __align__(16) ull g_Edup[D_DIM * K_CODES];  // [d][k] = {e,e} packed pairs

// ---- packed f32x2 helpers (sm_100+); each lane rounds like scalar op ----
__device__ __forceinline__ ull pk2(float a, float b) {
    ull r; asm("mov.b64 %0, {%1, %2};" : "=l"(r) : "f"(a), "f"(b)); return r;
}
__device__ __forceinline__ void upk2(ull v, float& a, float& b) {
    asm("mov.b64 {%0, %1}, %2;" : "=f"(a), "=f"(b) : "l"(v));
}
__device__ __forceinline__ ull ffma2(ull a, ull b, ull c) {
    ull r; asm("fma.rn.f32x2 %0, %1, %2, %3;" : "=l"(r) : "l"(a), "l"(b), "l"(c)); return r;
}
__device__ __forceinline__ ull add2(ull a, ull b) {
    ull r; asm("add.rn.f32x2 %0, %1, %2;" : "=l"(r) : "l"(a), "l"(b)); return r;
}

// Kernel 0: build duplicated transposed codebook + B_k chains; zero loss acc.
__global__ void __launch_bounds__(256) vq_prep(const float* __restrict__ emb) {
    int t = blockIdx.x * blockDim.x + threadIdx.x;   // 64*256 = 16384
    if (t == 0) g_loss_acc = 0.0;
    int k  = t >> 4;          // code 0..1023
    int dc = t & 15;          // d-chunk of 4
    float4 v = *(const float4*)(emb + (size_t)k * D_DIM + dc * 4);
    g_Edup[(size_t)(dc * 4 + 0) * K_CODES + k] = pk2(v.x, v.x);
    g_Edup[(size_t)(dc * 4 + 1) * K_CODES + k] = pk2(v.y, v.y);
    g_Edup[(size_t)(dc * 4 + 2) * K_CODES + k] = pk2(v.z, v.z);
    g_Edup[(size_t)(dc * 4 + 3) * K_CODES + k] = pk2(v.w, v.w);
    if (t < K_CODES) {
        const float* row = emb + (size_t)t * D_DIM;
        float b = 0.0f;
        #pragma unroll
        for (int i = 0; i < D_DIM; i++) b = __fmaf_rn(row[i], row[i], b);
        g_eB[t] = b;
    }
}

// Main kernel: one block = 128 positions of one image, all 1024 codes.
__global__ void __launch_bounds__(256, 2) vq_main(const float* __restrict__ x,
                                                  const float* __restrict__ emb,
                                                  float* __restrict__ out,
                                                  int out_size, int nblocks) {
    extern __shared__ char smem_raw[];
    float* Xs    = (float*)smem_raw;                       // [64][128]  32768 B
    ull*   EsDup = (ull*)(smem_raw + 32768);               // [64][130]  66560 B
    ull*   BsDup = (ull*)(smem_raw + 32768 + 66560);       // [128]       1024 B
    float* As    = (float*)(smem_raw + 100352);            // [128]        512 B
    int*   idx_s = (int*)(smem_raw + 100864);              // [128]        512 B
    // reduction overlays EsDup (only used after last chunk's compute):
    float* rV = (float*)EsDup;                             // [16][128]
    int*   rI = (int*)EsDup + 2048;                        // [16][128]

    const int tid = threadIdx.x;
    const int tx = tid & 15;            // position group 0..15 (8 positions)
    const int ty = tid >> 4;            // code group 0..15 (8 codes)
    const int b  = blockIdx.x >> 3;
    const int p0 = (blockIdx.x & 7) * TP;

    // ---- load X tile: Xs[d][pp] = x[(b*64+d)*1024 + p0 + pp] ----
    {
        const float* xb = x + (size_t)b * 65536 + p0;
        int lane = tid & 31;
        int r0 = tid >> 5;
        #pragma unroll
        for (int it = 0; it < 8; it++) {
            int d = r0 + it * 8;
            float4 v = *(const float4*)(xb + d * 1024 + lane * 4);
            *(float4*)&Xs[d * TP + lane * 4] = v;
        }
    }
    __syncthreads();

    // ---- A_p = sum(x^2): float2 leaves + binary tree (frozen order) ----
    if (tid < TP) {
        float l[32];
        #pragma unroll
        for (int t = 0; t < 32; t++) {
            float a = Xs[(2 * t) * TP + tid];
            float c = Xs[(2 * t + 1) * TP + tid];
            l[t] = __fmaf_rn(c, c, __fmul_rn(a, a));
        }
        #pragma unroll
        for (int off = 16; off >= 1; off >>= 1)
            #pragma unroll
            for (int t = 0; t < 16; t++)
                if (t < off) l[t] = __fadd_rn(l[t], l[t + off]);
        As[tid] = l[0];
    }
    __syncthreads();

    // per-thread packed A pairs (positions tx*8 .. tx*8+7)
    ull Apk[4];
    #pragma unroll
    for (int p2 = 0; p2 < 4; p2++)
        Apk[p2] = pk2(As[tx * 8 + 2 * p2], As[tx * 8 + 2 * p2 + 1]);
    const ull neg2 = pk2(-2.0f, -2.0f);

    float bv[8];
    int   bi[8];
    #pragma unroll
    for (int i = 0; i < 8; i++) { bv[i] = CUDART_INF_F; bi[i] = 0; }

    // ---- K chunks ----
    for (int kc = 0; kc < K_CODES / TK; kc++) {
        const int k0 = kc * TK;
        __syncthreads();   // previous chunk's compute done before overwrite

        // stage duplicated E chunk: EsDup[d][k] = {e,e}, k in [k0, k0+128)
        {
            int d    = tid >> 2;     // 0..63
            int part = tid & 3;      // 0..3 (32 pairs each)
            const ulonglong2* src = (const ulonglong2*)(g_Edup + (size_t)d * K_CODES + k0 + part * 32);
            ulonglong2*       dst = (ulonglong2*)(EsDup + (size_t)d * EROW + part * 32);
            #pragma unroll
            for (int j = 0; j < 16; j++) dst[j] = src[j];
            if (tid < TK) {
                float bk = g_eB[k0 + tid];
                BsDup[tid] = pk2(bk, bk);
            }
        }
        __syncthreads();

        // dot accumulators: 4 position-pairs x 8 codes, init 0
        ull acc[4][8];
        #pragma unroll
        for (int k = 0; k < 8; k++)
            #pragma unroll
            for (int p2 = 0; p2 < 4; p2++) acc[p2][k] = 0ull;

        #pragma unroll 8
        for (int d = 0; d < D_DIM; d++) {
            const ulonglong2* xp = (const ulonglong2*)(Xs + d * TP + tx * 8);
            ulonglong2 xa = xp[0];
            ulonglong2 xb2 = xp[1];
            const ulonglong2* ep = (const ulonglong2*)(EsDup + (size_t)d * EROW + ty * 8);
            ulonglong2 ea = ep[0], eb = ep[1], ec = ep[2], ed4 = ep[3];
            ull xs_[4] = { xa.x, xa.y, xb2.x, xb2.y };
            ull es_[8] = { ea.x, ea.y, eb.x, eb.y, ec.x, ec.y, ed4.x, ed4.y };
            #pragma unroll
            for (int k = 0; k < 8; k++)
                #pragma unroll
                for (int p2 = 0; p2 < 4; p2++)
                    acc[p2][k] = ffma2(xs_[p2], es_[k], acc[p2][k]);
        }

        // fold: d = fl(fl(A - 2M) + B), packed lanes == scalar bitwise.
        ull Bk[8];
        #pragma unroll
        for (int k = 0; k < 8; k++) Bk[k] = BsDup[ty * 8 + k];
        #pragma unroll
        for (int p2 = 0; p2 < 4; p2++) {
            int p = 2 * p2;
            #pragma unroll
            for (int k = 0; k < 8; k++) {
                ull dpk = add2(ffma2(neg2, acc[p2][k], Apk[p2]), Bk[k]);
                float d0, d1;
                upk2(dpk, d0, d1);
                int kk = k0 + ty * 8 + k;
                if (d0 < bv[p])     { bv[p] = d0;     bi[p] = kk; }
                if (d1 < bv[p + 1]) { bv[p + 1] = d1; bi[p + 1] = kk; }
            }
        }
    }

    // ---- cross-thread (ty) reduction per position: min, tie -> lowest idx ----
    __syncthreads();
    #pragma unroll
    for (int i = 0; i < 8; i++) {
        int p = tx * 8 + i;
        rV[ty * TP + p] = bv[i];
        rI[ty * TP + p] = bi[i];
    }
    __syncthreads();
    if (tid < TP) {
        float best = rV[tid];
        int besti  = rI[tid];
        #pragma unroll
        for (int t = 1; t < 16; t++) {
            float v = rV[t * TP + tid];
            int iv  = rI[t * TP + tid];
            if (v < best || (v == best && iv < besti)) { best = v; besti = iv; }
        }
        idx_s[tid] = besti;
        if (out_size >= TOTAL_OUT)
            out[ENC_OFF + b * 1024 + p0 + tid] = (float)besti;
    }
    __syncthreads();

    // ---- output (straight-through: x + fl(q - x)) + loss partial ----
    float lsum = 0.0f;
    #pragma unroll
    for (int j = 0; j < 32; j++) {
        int i  = tid + j * 256;
        int pp = i & 127;
        int d  = i >> 7;
        float q  = emb[(size_t)idx_s[pp] * 64 + d];
        float xv = Xs[d * TP + pp];
        float df = __fadd_rn(q, -xv);
        lsum += df * df;
        out[((size_t)b * 64 + d) * 1024 + p0 + pp] = __fadd_rn(xv, df);
    }
    #pragma unroll
    for (int off = 16; off > 0; off >>= 1)
        lsum += __shfl_down_sync(0xffffffffu, lsum, off);
    __shared__ float wsum[8];
    if ((tid & 31) == 0) wsum[tid >> 5] = lsum;
    __syncthreads();
    if (tid == 0) {
        float t = 0.0f;
        #pragma unroll
        for (int w = 0; w < 8; w++) t += wsum[w];
        atomicAdd(&g_loss_acc, (double)t);
        __threadfence();
        int old = atomicAdd(&g_done, 1);
        if (old == nblocks - 1) {               // last block finalizes
            g_done = 0;
            if (out_size >= TOTAL_OUT) {
                float m = (float)(g_loss_acc * (1.0 / 4194304.0));
                out[LOSS_OFF] = __fadd_rn(m, __fmul_rn(0.25f, m));
                out[NLL_OFF]  = 1.0f;
            }
        }
    }
}

extern "C" void kernel_launch(void* const* d_in, const int* in_sizes, int n_in,
                              void* d_out, int out_size) {
    const float* x   = (const float*)d_in[0];
    const float* emb = (const float*)d_in[1];
    if (n_in >= 2 && in_sizes[0] == K_CODES * D_DIM) {
        const float* t = x; x = emb; emb = t;
    }
    float* out = (float*)d_out;

    const int smem_bytes = 32768 + 66560 + 1024 + 512 + 512;   // 101376
    cudaFuncSetAttribute(vq_main, cudaFuncAttributeMaxDynamicSharedMemorySize,
                         smem_bytes);

    vq_prep<<<64, 256>>>(emb);
    vq_main<<<512, 256, smem_bytes>>>(x, emb, out, out_size, 512);
}

// round 4
// speedup vs baseline: 1.9053x; 1.9053x over previous
#include <cuda_runtime.h>
#include <math_constants.h>

// VQ-VAE vector quantizer. Bitwise-emulates the reference fp32 pipeline:
//   d_k = fl32( fl32(A - 2*M_k) + B_k )
//   A   = sum(x^2)  (float2 leaves + binary tree)   [frozen order]
//   M_k = x . e_k   (sequential ascending-d fp32 FMA chain from 0) [frozen]
//   B_k = sum(e^2)  (sequential ascending chain)    [frozen]
//   argmin, tie -> lowest index.
//
// R4: f32x2 lanes pair ADJACENT CODES (not positions): packed e comes free
// from contiguous LDS; only x needs {x,x} (4 MOV/d-step). acc[4][4]=32 regs
// -> no spills at 3 blocks/SM. XOR-swizzled E staging kills 8-way STS
// conflicts. TP=64, 1024 blocks.

#define K_CODES   1024
#define D_DIM     64
#define TP        64      // positions per block
#define TK        128     // codes per chunk
#define EROW      132     // Es row stride in floats (16B-aligned)
#define ENC_OFF   4194304
#define LOSS_OFF  4259840
#define NLL_OFF   4259841
#define TOTAL_OUT 4259842

typedef unsigned long long ull;

__device__ double g_loss_acc;
__device__ int    g_done;
__device__ float  g_eB[K_CODES];   // fp32 ||e_k||^2, sequential chain

// ---- packed f32x2 helpers (sm_100+); each lane rounds like scalar op ----
__device__ __forceinline__ ull pk2(float a, float b) {
    ull r; asm("mov.b64 %0, {%1, %2};" : "=l"(r) : "f"(a), "f"(b)); return r;
}
__device__ __forceinline__ void upk2(ull v, float& a, float& b) {
    asm("mov.b64 {%0, %1}, %2;" : "=f"(a), "=f"(b) : "l"(v));
}
__device__ __forceinline__ ull ffma2(ull a, ull b, ull c) {
    ull r; asm("fma.rn.f32x2 %0, %1, %2, %3;" : "=l"(r) : "l"(a), "l"(b), "l"(c)); return r;
}
__device__ __forceinline__ ull add2(ull a, ull b) {
    ull r; asm("add.rn.f32x2 %0, %1, %2;" : "=l"(r) : "l"(a), "l"(b)); return r;
}

// Kernel 0: B_k chains + zero loss accumulator.
__global__ void __launch_bounds__(256) vq_prep(const float* __restrict__ emb) {
    int k = blockIdx.x * blockDim.x + threadIdx.x;
    if (k == 0) g_loss_acc = 0.0;
    if (k < K_CODES) {
        const float* row = emb + (size_t)k * D_DIM;
        float b = 0.0f;
        #pragma unroll
        for (int i = 0; i < 16; i++) {
            float4 v = *(const float4*)(row + i * 4);
            b = __fmaf_rn(v.x, v.x, b);
            b = __fmaf_rn(v.y, v.y, b);
            b = __fmaf_rn(v.z, v.z, b);
            b = __fmaf_rn(v.w, v.w, b);
        }
        g_eB[k] = b;
    }
}

// Main kernel: one block = 64 positions of one image, all 1024 codes.
__global__ void __launch_bounds__(256, 3) vq_main(const float* __restrict__ x,
                                                  const float* __restrict__ emb,
                                                  float* __restrict__ out,
                                                  int out_size, int nblocks) {
    extern __shared__ char smem_raw[];
    float* Xs   = (float*)smem_raw;                       // [64][64]   16384 B
    float* Es   = (float*)(smem_raw + 16384);             // [64][132]  33792 B (swizzled)
    float* Bs   = (float*)(smem_raw + 16384 + 33792);     // [128]        512 B
    float* As   = Bs + TK;                                // [64]         256 B
    int*   idx_s = (int*)(As + TP);                       // [64]         256 B
    // reduction overlays Es (only used after last chunk's compute):
    float* rV = Es;                                       // [16][64]
    int*   rI = (int*)Es + 1024;                          // [16][64]

    const int tid = threadIdx.x;
    const int tx = tid & 15;            // position group (4 positions)
    const int ty = tid >> 4;            // code group (8 codes)
    const int b  = blockIdx.x >> 4;
    const int p0 = (blockIdx.x & 15) * TP;

    // ---- load X tile: Xs[d][pp] = x[(b*64+d)*1024 + p0 + pp] ----
    {
        const float* xb = x + (size_t)b * 65536 + p0;
        int chunk = tid & 15;           // 16 float4 per row of 64
        int r0    = tid >> 4;           // 16 rows per iter
        #pragma unroll
        for (int it = 0; it < 4; it++) {
            int d = r0 + it * 16;
            float4 v = *(const float4*)(xb + d * 1024 + chunk * 4);
            *(float4*)&Xs[d * TP + chunk * 4] = v;
        }
    }
    __syncthreads();

    // ---- A_p = sum(x^2): float2 leaves + binary tree (frozen order) ----
    if (tid < TP) {
        float l[32];
        #pragma unroll
        for (int t = 0; t < 32; t++) {
            float a = Xs[(2 * t) * TP + tid];
            float c = Xs[(2 * t + 1) * TP + tid];
            l[t] = __fmaf_rn(c, c, __fmul_rn(a, a));
        }
        #pragma unroll
        for (int off = 16; off >= 1; off >>= 1)
            #pragma unroll
            for (int t = 0; t < 16; t++)
                if (t < off) l[t] = __fadd_rn(l[t], l[t + off]);
        As[tid] = l[0];
    }

    const ull neg2 = pk2(-2.0f, -2.0f);
    float bv[4];
    int   bi[4];
    #pragma unroll
    for (int i = 0; i < 4; i++) { bv[i] = CUDART_INF_F; bi[i] = 0; }

    // staging swizzle constant for this thread: s = dc>>1 (dc = tid&15)
    const int st_dc = tid & 15;
    const int st_s  = st_dc >> 1;

    // ---- K chunks ----
    for (int kc = 0; kc < K_CODES / TK; kc++) {
        const int k0 = kc * TK;
        __syncthreads();   // As ready / previous chunk compute done

        // stage E chunk transposed + granule-XOR swizzled:
        //   element (d, k) -> word  d*EROW + (((k>>2) ^ (d>>3)) << 2) + (k&3)
        {
            int krow = tid >> 4;
            #pragma unroll
            for (int it = 0; it < 8; it++) {
                int k = krow + it * 16;
                float4 v = *(const float4*)(emb + (size_t)(k0 + k) * 64 + st_dc * 4);
                int swc = ((((k >> 2) ^ st_s) << 2) + (k & 3));
                Es[(st_dc * 4 + 0) * EROW + swc] = v.x;
                Es[(st_dc * 4 + 1) * EROW + swc] = v.y;
                Es[(st_dc * 4 + 2) * EROW + swc] = v.z;
                Es[(st_dc * 4 + 3) * EROW + swc] = v.w;
            }
            if (tid < TK) Bs[tid] = g_eB[k0 + tid];
        }
        __syncthreads();

        // dot accumulators: 4 positions x 4 code-pairs, init 0
        ull acc[4][4];
        #pragma unroll
        for (int p = 0; p < 4; p++)
            #pragma unroll
            for (int kk = 0; kk < 4; kk++) acc[p][kk] = 0ull;

        #pragma unroll
        for (int d8 = 0; d8 < 8; d8++) {
            // swizzled granules for this d-group (constant across inner j)
            const int ga = (2 * ty)     ^ d8;   // codes ty*8   .. +3
            const int gb = (2 * ty + 1) ^ d8;   // codes ty*8+4 .. +7
            #pragma unroll
            for (int j = 0; j < 8; j++) {
                const int d = d8 * 8 + j;
                float4 xv = *(const float4*)&Xs[d * TP + tx * 4];
                ulonglong2 e01 = *(const ulonglong2*)&Es[d * EROW + ga * 4];
                ulonglong2 e23 = *(const ulonglong2*)&Es[d * EROW + gb * 4];
                ull ep[4] = { e01.x, e01.y, e23.x, e23.y };
                float xs4[4] = { xv.x, xv.y, xv.z, xv.w };
                #pragma unroll
                for (int p = 0; p < 4; p++) {
                    ull xp = pk2(xs4[p], xs4[p]);
                    #pragma unroll
                    for (int kk = 0; kk < 4; kk++)
                        acc[p][kk] = ffma2(xp, ep[kk], acc[p][kk]);
                }
            }
        }

        // fold: d = fl(fl(A - 2M) + B); even code first -> lowest index on tie
        #pragma unroll
        for (int p = 0; p < 4; p++) {
            float Ap = As[tx * 4 + p];
            ull Apk = pk2(Ap, Ap);
            #pragma unroll
            for (int kk = 0; kk < 4; kk++) {
                ull B2 = ((const ull*)Bs)[ty * 4 + kk];
                ull dpk = add2(ffma2(neg2, acc[p][kk], Apk), B2);
                float d0, d1;
                upk2(dpk, d0, d1);
                int ke = k0 + ty * 8 + 2 * kk;
                if (d0 < bv[p]) { bv[p] = d0; bi[p] = ke; }
                if (d1 < bv[p]) { bv[p] = d1; bi[p] = ke + 1; }
            }
        }
    }

    // ---- cross-thread (ty) reduction per position: min, tie -> lowest idx ----
    __syncthreads();
    #pragma unroll
    for (int p = 0; p < 4; p++) {
        rV[ty * TP + tx * 4 + p] = bv[p];
        rI[ty * TP + tx * 4 + p] = bi[p];
    }
    __syncthreads();
    if (tid < TP) {
        float best = rV[tid];
        int besti  = rI[tid];
        #pragma unroll
        for (int t = 1; t < 16; t++) {
            float v = rV[t * TP + tid];
            int iv  = rI[t * TP + tid];
            if (v < best || (v == best && iv < besti)) { best = v; besti = iv; }
        }
        idx_s[tid] = besti;
        if (out_size >= TOTAL_OUT)
            out[ENC_OFF + b * 1024 + p0 + tid] = (float)besti;
    }
    __syncthreads();

    // ---- output (straight-through: x + fl(q - x)) + loss partial ----
    float lsum = 0.0f;
    #pragma unroll
    for (int j = 0; j < 16; j++) {
        int i  = tid + j * 256;
        int pp = i & 63;
        int d  = i >> 6;
        float q  = emb[(size_t)idx_s[pp] * 64 + d];
        float xv = Xs[d * TP + pp];
        float df = __fadd_rn(q, -xv);
        lsum += df * df;
        out[((size_t)b * 64 + d) * 1024 + p0 + pp] = __fadd_rn(xv, df);
    }
    #pragma unroll
    for (int off = 16; off > 0; off >>= 1)
        lsum += __shfl_down_sync(0xffffffffu, lsum, off);
    __shared__ float wsum[8];
    if ((tid & 31) == 0) wsum[tid >> 5] = lsum;
    __syncthreads();
    if (tid == 0) {
        float t = 0.0f;
        #pragma unroll
        for (int w = 0; w < 8; w++) t += wsum[w];
        atomicAdd(&g_loss_acc, (double)t);
        __threadfence();
        int old = atomicAdd(&g_done, 1);
        if (old == nblocks - 1) {               // last block finalizes
            g_done = 0;
            if (out_size >= TOTAL_OUT) {
                float m = (float)(g_loss_acc * (1.0 / 4194304.0));
                out[LOSS_OFF] = __fadd_rn(m, __fmul_rn(0.25f, m));
                out[NLL_OFF]  = 1.0f;
            }
        }
    }
}

extern "C" void kernel_launch(void* const* d_in, const int* in_sizes, int n_in,
                              void* d_out, int out_size) {
    const float* x   = (const float*)d_in[0];
    const float* emb = (const float*)d_in[1];
    if (n_in >= 2 && in_sizes[0] == K_CODES * D_DIM) {
        const float* t = x; x = emb; emb = t;
    }
    float* out = (float*)d_out;

    const int smem_bytes = 16384 + 33792 + 512 + 256 + 256;   // 51200
    cudaFuncSetAttribute(vq_main, cudaFuncAttributeMaxDynamicSharedMemorySize,
                         smem_bytes);

    vq_prep<<<4, 256>>>(emb);
    vq_main<<<1024, 256, smem_bytes>>>(x, emb, out, out_size, 1024);
}